// round 3
// baseline (speedup 1.0000x reference)
#include <cuda_runtime.h>
#include <cstdint>

#define H 256
#define NMAX 100000
#define EMAX 320000

// Scratch (allocation-free rule: __device__ globals)
__device__ float        g_agg[3][NMAX * H];   // 307 MB scatter accumulators
__device__ float        g_score[3][EMAX];     // raw scores, then exp(score-max)
__device__ unsigned int g_menc[3][NMAX];      // monotone-encoded segment max
__device__ float        g_ssum[3][NMAX];      // segment softmax denominators

// monotone float<->uint mapping so atomicMax works for signed floats
__device__ __forceinline__ unsigned enc_f(float f) {
    unsigned u = __float_as_uint(f);
    return (u & 0x80000000u) ? ~u : (u | 0x80000000u);
}
__device__ __forceinline__ float dec_f(unsigned u) {
    return (u & 0x80000000u) ? __uint_as_float(u ^ 0x80000000u)
                             : __uint_as_float(~u);
}

__device__ __forceinline__ void red_add_v4(float* p, float4 v) {
    asm volatile("red.global.add.v4.f32 [%0], {%1,%2,%3,%4};"
                 :: "l"(p), "f"(v.x), "f"(v.y), "f"(v.z), "f"(v.w) : "memory");
}

// ---------------------------------------------------------------- init
__global__ void k_init(int N) {
    size_t stride = (size_t)gridDim.x * blockDim.x;
    size_t tid0 = (size_t)blockIdx.x * blockDim.x + threadIdx.x;
    size_t nf4 = (size_t)N * (H / 4);
    for (size_t i = tid0; i < 3 * nf4; i += stride) {
        int g = (int)(i / nf4);
        size_t r = i - (size_t)g * nf4;
        reinterpret_cast<float4*>(g_agg[g])[r] = make_float4(0.f, 0.f, 0.f, 0.f);
    }
    for (size_t i = tid0; i < (size_t)3 * N; i += stride) {
        int g = (int)(i / (size_t)N);
        size_t r = i - (size_t)g * (size_t)N;
        g_menc[g][r] = 0x007FFFFFu;  // enc(-inf)
        g_ssum[g][r] = 0.f;
    }
}

// ---------------------------------------------------------------- pass 1: scores + segment max
__global__ void k_scores(const float* __restrict__ ent, const float* __restrict__ rel,
                         const int* __restrict__ src, const int* __restrict__ dst,
                         const int* __restrict__ rid, const int* __restrict__ nid, int E) {
    int e = blockIdx.x * 8 + (threadIdx.x >> 5);
    if (e >= E) return;
    int lane = threadIdx.x & 31;
    int d = dst[e];
    int sn = nid[src[e]];
    int dn = nid[d];
    const float4* hs = reinterpret_cast<const float4*>(ent + (size_t)sn * H);
    const float4* hd = reinterpret_cast<const float4*>(ent + (size_t)dn * H);
    const float4* ef = reinterpret_cast<const float4*>(rel + (size_t)rid[e] * H);
    float de = 0.f, dnn = 0.f, dc = 0.f;
#pragma unroll
    for (int q = 0; q < 2; q++) {
        int i = lane + 32 * q;
        float4 a = hs[i], b = hd[i], c = ef[i];
        de  += c.x * b.x + c.y * b.y + c.z * b.z + c.w * b.w;
        dnn += a.x * b.x + a.y * b.y + a.z * b.z + a.w * b.w;
        dc  += a.x * c.x * b.x + a.y * c.y * b.y + a.z * c.z * b.z + a.w * c.w * b.w;
    }
#pragma unroll
    for (int o = 16; o; o >>= 1) {
        de  += __shfl_xor_sync(0xffffffffu, de, o);
        dnn += __shfl_xor_sync(0xffffffffu, dnn, o);
        dc  += __shfl_xor_sync(0xffffffffu, dc, o);
    }
    if (lane == 0) {
        g_score[0][e] = de;
        g_score[1][e] = dnn;
        g_score[2][e] = dc;
        atomicMax(&g_menc[0][d], enc_f(de));
        atomicMax(&g_menc[1][d], enc_f(dnn));
        atomicMax(&g_menc[2][d], enc_f(dc));
    }
}

// ---------------------------------------------------------------- pass 2: exp + segment sum
__global__ void k_exps(const int* __restrict__ dst, int E) {
    int e = blockIdx.x * blockDim.x + threadIdx.x;
    if (e >= E) return;
    int d = dst[e];
#pragma unroll
    for (int k = 0; k < 3; k++) {
        float m = dec_f(g_menc[k][d]);
        float ex = expf(g_score[k][e] - m);
        g_score[k][e] = ex;
        atomicAdd(&g_ssum[k][d], ex);
    }
}

// ---------------------------------------------------------------- pass 3: normalized scatter (vectorized reds)
__global__ void k_scatter(const float* __restrict__ ent, const float* __restrict__ rel,
                          const int* __restrict__ src, const int* __restrict__ dst,
                          const int* __restrict__ rid, const int* __restrict__ nid, int E) {
    int e = blockIdx.x * 8 + (threadIdx.x >> 5);
    if (e >= E) return;
    int lane = threadIdx.x & 31;
    int d = dst[e];
    int sn = nid[src[e]];
    float c0 = g_score[0][e] / g_ssum[0][d];
    float c1 = g_score[1][e] / g_ssum[1][d];
    float c2 = g_score[2][e] / g_ssum[2][d];
    const float4* hs = reinterpret_cast<const float4*>(ent + (size_t)sn * H);
    const float4* ef = reinterpret_cast<const float4*>(rel + (size_t)rid[e] * H);
    float* a0 = g_agg[0] + (size_t)d * H;
    float* a1 = g_agg[1] + (size_t)d * H;
    float* a2 = g_agg[2] + (size_t)d * H;
#pragma unroll
    for (int q = 0; q < 2; q++) {
        int i = lane + 32 * q;
        float4 s = hs[i], t = ef[i];
        red_add_v4(a0 + 4 * i, make_float4(t.x * c0, t.y * c0, t.z * c0, t.w * c0));
        red_add_v4(a1 + 4 * i, make_float4(s.x * c1, s.y * c1, s.z * c1, s.w * c1));
        red_add_v4(a2 + 4 * i, make_float4(s.x * t.x * c2, s.y * t.y * c2,
                                           s.z * t.z * c2, s.w * t.w * c2));
    }
}

// ---------------------------------------------------------------- pass 4: three fused GEMMs + tanh + residual
// C_g = agg_g @ W_g; out_ent = ent + sum_g tanh(C_g). fp32 via packed fma.rn.f32x2.
__global__ __launch_bounds__(256, 2) void k_gemm_ent(
    const float* __restrict__ ent,
    const float* __restrict__ w0, const float* __restrict__ w1, const float* __restrict__ w2,
    float* __restrict__ out, int N) {
    __shared__ float As[32][68];    // transposed A tile [k][m], padded
    __shared__ float Ws[32][128];   // W tile [k][n]
    const int tid = threadIdx.x;
    const int tn = tid & 15;        // column group (interleaved pairs)
    const int tm = tid >> 4;        // row group (4 rows each)
    const int m0 = blockIdx.x * 64;
    const int n0 = blockIdx.y * 128;

    float osum[4][8];
#pragma unroll
    for (int i = 0; i < 4; i++)
#pragma unroll
        for (int j = 0; j < 8; j++) osum[i][j] = 0.f;

#pragma unroll 1
    for (int g = 0; g < 3; g++) {
        const float* A = g_agg[g];
        const float* Wm = (g == 0) ? w0 : (g == 1) ? w1 : w2;
        unsigned long long acc[4][4];
#pragma unroll
        for (int i = 0; i < 4; i++)
#pragma unroll
            for (int p = 0; p < 4; p++) acc[i][p] = 0ull;

#pragma unroll 1
        for (int k0 = 0; k0 < H; k0 += 32) {
            // A tile -> transposed smem
#pragma unroll
            for (int q = 0; q < 2; q++) {
                int f4 = tid * 2 + q;
                int row = f4 >> 3;
                int c4 = f4 & 7;
                float4 v = make_float4(0.f, 0.f, 0.f, 0.f);
                int gr = m0 + row;
                if (gr < N)
                    v = *reinterpret_cast<const float4*>(A + (size_t)gr * H + k0 + c4 * 4);
                As[c4 * 4 + 0][row] = v.x;
                As[c4 * 4 + 1][row] = v.y;
                As[c4 * 4 + 2][row] = v.z;
                As[c4 * 4 + 3][row] = v.w;
            }
            // W tile
#pragma unroll
            for (int q = 0; q < 4; q++) {
                int idx = tid + q * 256;
                int row = idx >> 5;
                int c4 = idx & 31;
                *reinterpret_cast<float4*>(&Ws[row][c4 * 4]) =
                    *reinterpret_cast<const float4*>(Wm + (size_t)(k0 + row) * H + n0 + c4 * 4);
            }
            __syncthreads();
#pragma unroll
            for (int kk = 0; kk < 32; kk++) {
                unsigned long long ad[4], wv[4];
#pragma unroll
                for (int i = 0; i < 4; i++) {
                    float a = As[kk][tm * 4 + i];
                    asm("mov.b64 %0, {%1, %1};" : "=l"(ad[i]) : "f"(a));
                }
#pragma unroll
                for (int p = 0; p < 4; p++)
                    wv[p] = *reinterpret_cast<const unsigned long long*>(&Ws[kk][2 * (tn + 16 * p)]);
#pragma unroll
                for (int i = 0; i < 4; i++)
#pragma unroll
                    for (int p = 0; p < 4; p++)
                        asm("fma.rn.f32x2 %0, %1, %2, %0;"
                            : "+l"(acc[i][p]) : "l"(ad[i]), "l"(wv[p]));
            }
            __syncthreads();
        }
        // epilogue for this GEMM: tanh + accumulate
#pragma unroll
        for (int i = 0; i < 4; i++)
#pragma unroll
            for (int p = 0; p < 4; p++) {
                float2 f = *reinterpret_cast<float2*>(&acc[i][p]);
                osum[i][2 * p]     += tanhf(f.x);
                osum[i][2 * p + 1] += tanhf(f.y);
            }
    }
    // residual + store
#pragma unroll
    for (int i = 0; i < 4; i++) {
        int row = m0 + tm * 4 + i;
        if (row < N) {
#pragma unroll
            for (int p = 0; p < 4; p++) {
                int col = n0 + 2 * (tn + 16 * p);
                const float2 ev = *reinterpret_cast<const float2*>(ent + (size_t)row * H + col);
                float2 o = make_float2(ev.x + osum[i][2 * p], ev.y + osum[i][2 * p + 1]);
                *reinterpret_cast<float2*>(out + (size_t)row * H + col) = o;
            }
        }
    }
}

// ---------------------------------------------------------------- pass 5: out_rel = rel_emb @ rel_w
__global__ void k_rel(const float* __restrict__ rel, const float* __restrict__ rw,
                      float* __restrict__ out, int R2) {
    __shared__ float row[H];
    int r = blockIdx.x;
    int tid = threadIdx.x;
    row[tid] = rel[(size_t)r * H + tid];
    __syncthreads();
    float acc = 0.f;
#pragma unroll 8
    for (int k = 0; k < H; k++)
        acc += row[k] * rw[(size_t)k * H + tid];
    out[(size_t)r * H + tid] = acc;
}

// ---------------------------------------------------------------- launch
extern "C" void kernel_launch(void* const* d_in, const int* in_sizes, int n_in,
                              void* d_out, int out_size) {
    const float* ent    = (const float*)d_in[0];
    const float* rel    = (const float*)d_in[1];
    const float* w_edge = (const float*)d_in[2];
    const float* w_node = (const float*)d_in[3];
    const float* w_comp = (const float*)d_in[4];
    const float* rel_w  = (const float*)d_in[5];
    const int* src = (const int*)d_in[6];
    const int* dst = (const int*)d_in[7];
    const int* rid = (const int*)d_in[8];
    const int* nid = (const int*)d_in[9];
    const int N  = in_sizes[0] / H;
    const int R2 = in_sizes[1] / H;
    const int E  = in_sizes[6];
    float* out_ent = (float*)d_out;
    float* out_rel = out_ent + (size_t)N * H;

    k_init<<<2048, 256>>>(N);
    k_scores<<<(E + 7) / 8, 256>>>(ent, rel, src, dst, rid, nid, E);
    k_exps<<<(E + 255) / 256, 256>>>(dst, E);
    k_scatter<<<(E + 7) / 8, 256>>>(ent, rel, src, dst, rid, nid, E);
    dim3 gg((N + 63) / 64, 2);
    k_gemm_ent<<<gg, 256>>>(ent, w_edge, w_node, w_comp, out_ent, N);
    if (R2 > 0) k_rel<<<R2, 256>>>(rel, rel_w, out_rel, R2);
}

// round 6
// speedup vs baseline: 1.5773x; 1.5773x over previous
#include <cuda_runtime.h>
#include <cuda_bf16.h>
#include <cstdint>

#define H 256
#define NMAX 100000
#define EMAX 320000

// ---------------- scratch (__device__ globals; no allocation allowed) --------
__device__ float          g_agg[3][NMAX * H];   // scatter accumulators (fp32)
__device__ float          g_score[3][EMAX];
__device__ unsigned int   g_menc[3][NMAX];
__device__ float          g_ssum[3][NMAX];
__device__ unsigned short g_wh[3][H * H];       // W^T hi (bf16 bits), [n][k]
__device__ unsigned short g_wl[3][H * H];       // W^T lo (bf16 bits)

// ---------------- small helpers ---------------------------------------------
__device__ __forceinline__ unsigned enc_f(float f) {
    unsigned u = __float_as_uint(f);
    return (u & 0x80000000u) ? ~u : (u | 0x80000000u);
}
__device__ __forceinline__ float dec_f(unsigned u) {
    return (u & 0x80000000u) ? __uint_as_float(u ^ 0x80000000u)
                             : __uint_as_float(~u);
}
__device__ __forceinline__ void red_add_v4(float* p, float4 v) {
    asm volatile("red.global.add.v4.f32 [%0], {%1,%2,%3,%4};"
                 :: "l"(p), "f"(v.x), "f"(v.y), "f"(v.z), "f"(v.w) : "memory");
}
__device__ __forceinline__ uint32_t smem_u32(const void* p) {
    uint32_t a;
    asm("{ .reg .u64 t; cvta.to.shared.u64 t, %1; cvt.u32.u64 %0, t; }"
        : "=r"(a) : "l"(p));
    return a;
}
__device__ __forceinline__ void ldsm_x4(uint32_t r[4], uint32_t addr) {
    asm volatile("ldmatrix.sync.aligned.m8n8.x4.shared.b16 {%0,%1,%2,%3}, [%4];"
                 : "=r"(r[0]), "=r"(r[1]), "=r"(r[2]), "=r"(r[3]) : "r"(addr));
}
__device__ __forceinline__ void mma_bf16(float d[4], const uint32_t a[4],
                                         const uint32_t b[2]) {
    asm volatile(
        "mma.sync.aligned.m16n8k16.row.col.f32.bf16.bf16.f32 "
        "{%0,%1,%2,%3}, {%4,%5,%6,%7}, {%8,%9}, {%0,%1,%2,%3};"
        : "+f"(d[0]), "+f"(d[1]), "+f"(d[2]), "+f"(d[3])
        : "r"(a[0]), "r"(a[1]), "r"(a[2]), "r"(a[3]), "r"(b[0]), "r"(b[1]));
}
__device__ __forceinline__ void cp16(uint32_t dst, const void* src) {
    asm volatile("cp.async.cg.shared.global [%0], [%1], 16;"
                 :: "r"(dst), "l"(src) : "memory");
}
#define CP_COMMIT asm volatile("cp.async.commit_group;" ::: "memory")
#define CP_WAIT0  asm volatile("cp.async.wait_group 0;" ::: "memory")

// ---------------------------------------------------------------- init
__global__ void k_init(int N) {
    size_t stride = (size_t)gridDim.x * blockDim.x;
    size_t tid0 = (size_t)blockIdx.x * blockDim.x + threadIdx.x;
    size_t nf4 = (size_t)N * (H / 4);
    for (size_t i = tid0; i < 3 * nf4; i += stride) {
        int g = (int)(i / nf4);
        size_t r = i - (size_t)g * nf4;
        reinterpret_cast<float4*>(g_agg[g])[r] = make_float4(0.f, 0.f, 0.f, 0.f);
    }
    for (size_t i = tid0; i < (size_t)3 * N; i += stride) {
        int g = (int)(i / (size_t)N);
        size_t r = i - (size_t)g * (size_t)N;
        g_menc[g][r] = 0x007FFFFFu;
        g_ssum[g][r] = 0.f;
    }
}

// ------------------------------------------------- W -> W^T bf16 hi/lo split
__global__ void k_wconv(const float* __restrict__ w0, const float* __restrict__ w1,
                        const float* __restrict__ w2) {
    int i = blockIdx.x * blockDim.x + threadIdx.x;
    if (i >= 3 * H * H) return;
    int g = i >> 16;
    int r = i & 0xFFFF;
    int k = r >> 8, n = r & 255;
    const float* w = (g == 0) ? w0 : (g == 1) ? w1 : w2;
    float v = w[k * H + n];
    __nv_bfloat16 hi = __float2bfloat16(v);
    float lo = v - __bfloat162float(hi);
    g_wh[g][n * H + k] = __bfloat16_as_ushort(hi);
    g_wl[g][n * H + k] = __bfloat16_as_ushort(__float2bfloat16(lo));
}

// ---------------------------------------------------------------- pass 1: scores + segment max
__global__ void k_scores(const float* __restrict__ ent, const float* __restrict__ rel,
                         const int* __restrict__ src, const int* __restrict__ dst,
                         const int* __restrict__ rid, const int* __restrict__ nid, int E) {
    int e = blockIdx.x * 8 + (threadIdx.x >> 5);
    if (e >= E) return;
    int lane = threadIdx.x & 31;
    int d = dst[e];
    int sn = nid[src[e]];
    int dn = nid[d];
    const float4* hs = reinterpret_cast<const float4*>(ent + (size_t)sn * H);
    const float4* hd = reinterpret_cast<const float4*>(ent + (size_t)dn * H);
    const float4* ef = reinterpret_cast<const float4*>(rel + (size_t)rid[e] * H);
    float de = 0.f, dnn = 0.f, dc = 0.f;
#pragma unroll
    for (int q = 0; q < 2; q++) {
        int i = lane + 32 * q;
        float4 a = hs[i], b = hd[i], c = ef[i];
        de  += c.x * b.x + c.y * b.y + c.z * b.z + c.w * b.w;
        dnn += a.x * b.x + a.y * b.y + a.z * b.z + a.w * b.w;
        dc  += a.x * c.x * b.x + a.y * c.y * b.y + a.z * c.z * b.z + a.w * c.w * b.w;
    }
#pragma unroll
    for (int o = 16; o; o >>= 1) {
        de  += __shfl_xor_sync(0xffffffffu, de, o);
        dnn += __shfl_xor_sync(0xffffffffu, dnn, o);
        dc  += __shfl_xor_sync(0xffffffffu, dc, o);
    }
    if (lane == 0) {
        g_score[0][e] = de;
        g_score[1][e] = dnn;
        g_score[2][e] = dc;
        atomicMax(&g_menc[0][d], enc_f(de));
        atomicMax(&g_menc[1][d], enc_f(dnn));
        atomicMax(&g_menc[2][d], enc_f(dc));
    }
}

// ---------------------------------------------------------------- pass 2: exp + segment sum
__global__ void k_exps(const int* __restrict__ dst, int E) {
    int e = blockIdx.x * blockDim.x + threadIdx.x;
    if (e >= E) return;
    int d = dst[e];
#pragma unroll
    for (int k = 0; k < 3; k++) {
        float m = dec_f(g_menc[k][d]);
        float ex = expf(g_score[k][e] - m);
        g_score[k][e] = ex;
        atomicAdd(&g_ssum[k][d], ex);
    }
}

// ---------------------------------------------------------------- pass 3: normalized scatter
__global__ void k_scatter(const float* __restrict__ ent, const float* __restrict__ rel,
                          const int* __restrict__ src, const int* __restrict__ dst,
                          const int* __restrict__ rid, const int* __restrict__ nid, int E) {
    int e = blockIdx.x * 8 + (threadIdx.x >> 5);
    if (e >= E) return;
    int lane = threadIdx.x & 31;
    int d = dst[e];
    int sn = nid[src[e]];
    float c0 = g_score[0][e] / g_ssum[0][d];
    float c1 = g_score[1][e] / g_ssum[1][d];
    float c2 = g_score[2][e] / g_ssum[2][d];
    const float4* hs = reinterpret_cast<const float4*>(ent + (size_t)sn * H);
    const float4* ef = reinterpret_cast<const float4*>(rel + (size_t)rid[e] * H);
    float* a0 = g_agg[0] + (size_t)d * H;
    float* a1 = g_agg[1] + (size_t)d * H;
    float* a2 = g_agg[2] + (size_t)d * H;
#pragma unroll
    for (int q = 0; q < 2; q++) {
        int i = lane + 32 * q;
        float4 s = hs[i], t = ef[i];
        red_add_v4(a0 + 4 * i, make_float4(t.x * c0, t.y * c0, t.z * c0, t.w * c0));
        red_add_v4(a1 + 4 * i, make_float4(s.x * c1, s.y * c1, s.z * c1, s.w * c1));
        red_add_v4(a2 + 4 * i, make_float4(s.x * t.x * c2, s.y * t.y * c2,
                                           s.z * t.z * c2, s.w * t.w * c2));
    }
}

// ---------------------------------------------------------------- pass 4: mma.sync split-bf16 GEMM
// CTA: 128x128 tile of out_ent; 512 threads = 16 warps (4m x 4n), warp tile 32x32.
// For g in {0,1,2}: D = Ah@Bh + Ah@Bl + Al@Bh (f32 acc), tanh folded per g.
#define PCH 72                               // smem pitch (bf16 elems) = 144 B
#define KC 64
#define TILE_BYTES (128 * PCH * 2)           // 18432
#define STAGE_BYTES (4 * TILE_BYTES)         // Ah | Al | Bh | Bl = 73728
#define GEMM_SMEM (2 * STAGE_BYTES)          // 147456

__device__ __forceinline__ void ldg_A(float4 av[2][2], int g, int c, int m0, int N) {
    const float* A = g_agg[g];
    const int k0 = c * KC;
    const int tid = threadIdx.x;
#pragma unroll
    for (int q = 0; q < 2; q++) {
        int idx = q * 512 + tid;
        int row = idx >> 3, oct = idx & 7;
        int gr = m0 + row;
        if (gr < N) {
            const float4* p = reinterpret_cast<const float4*>(
                A + (size_t)gr * H + k0 + oct * 8);
            av[q][0] = p[0];
            av[q][1] = p[1];
        } else {
            av[q][0] = make_float4(0.f, 0.f, 0.f, 0.f);
            av[q][1] = make_float4(0.f, 0.f, 0.f, 0.f);
        }
    }
}
__device__ __forceinline__ void split2(float x, float y, uint32_t& h, uint32_t& l) {
    __nv_bfloat16 hx = __float2bfloat16(x), hy = __float2bfloat16(y);
    __nv_bfloat16 lx = __float2bfloat16(x - __bfloat162float(hx));
    __nv_bfloat16 ly = __float2bfloat16(y - __bfloat162float(hy));
    h = ((uint32_t)__bfloat16_as_ushort(hy) << 16) | __bfloat16_as_ushort(hx);
    l = ((uint32_t)__bfloat16_as_ushort(ly) << 16) | __bfloat16_as_ushort(lx);
}
__device__ __forceinline__ void sts_A(const float4 av[2][2], char* stage) {
    const int tid = threadIdx.x;
#pragma unroll
    for (int q = 0; q < 2; q++) {
        int idx = q * 512 + tid;
        int row = idx >> 3, oct = idx & 7;
        uint4 hi, lo;
        split2(av[q][0].x, av[q][0].y, hi.x, lo.x);
        split2(av[q][0].z, av[q][0].w, hi.y, lo.y);
        split2(av[q][1].x, av[q][1].y, hi.z, lo.z);
        split2(av[q][1].z, av[q][1].w, hi.w, lo.w);
        uint32_t off = (uint32_t)(row * (PCH * 2) + oct * 16);
        *reinterpret_cast<uint4*>(stage + off) = hi;
        *reinterpret_cast<uint4*>(stage + TILE_BYTES + off) = lo;
    }
}
__device__ __forceinline__ void cpB(int g, int c, int n0, uint32_t stage_sb) {
    const int tid = threadIdx.x;
    const int k0 = c * KC;
#pragma unroll
    for (int q = 0; q < 2; q++) {
        int idx = q * 512 + tid;
        int row = idx >> 3, oct = idx & 7;
        uint32_t off = (uint32_t)(row * (PCH * 2) + oct * 16);
        size_t gi = (size_t)(n0 + row) * H + k0 + oct * 8;
        cp16(stage_sb + 2 * TILE_BYTES + off, g_wh[g] + gi);
        cp16(stage_sb + 3 * TILE_BYTES + off, g_wl[g] + gi);
    }
}

__global__ __launch_bounds__(512, 1)
void k_gemm_mma(const float* __restrict__ ent, float* __restrict__ out, int N) {
    extern __shared__ char smem[];
    const uint32_t sb = smem_u32(smem);
    const int tid = threadIdx.x;
    const int lane = tid & 31, wid = tid >> 5;
    const int wm = wid >> 2, wn = wid & 3;
    const int mbase = wm * 32, nbase = wn * 32;
    const int m0 = blockIdx.y * 128, n0 = blockIdx.x * 128;

    // ldmatrix per-lane address components
    const int a_row = (lane & 7) + ((lane >> 3) & 1) * 8;  // m within 16
    const int a_kof = (lane >> 4) * 8;                     // k half
    const int b_row = (lane & 7) + (lane >> 4) * 8;        // n within 16 (2 frags)
    const int b_kof = ((lane >> 3) & 1) * 8;               // k half

    float osum[2][4][4];
#pragma unroll
    for (int f = 0; f < 2; f++)
#pragma unroll
        for (int nf = 0; nf < 4; nf++)
#pragma unroll
            for (int i = 0; i < 4; i++) osum[f][nf][i] = 0.f;

#pragma unroll 1
    for (int g = 0; g < 3; g++) {
        float acc[2][4][4];
#pragma unroll
        for (int f = 0; f < 2; f++)
#pragma unroll
            for (int nf = 0; nf < 4; nf++)
#pragma unroll
                for (int i = 0; i < 4; i++) acc[f][nf][i] = 0.f;

        float4 av[2][2];
        // prologue: chunk 0 -> buf 0
        ldg_A(av, g, 0, m0, N);
        cpB(g, 0, n0, sb);
        CP_COMMIT;
        sts_A(av, smem);
        CP_WAIT0;
        __syncthreads();

#pragma unroll 1
        for (int c = 0; c < 4; c++) {
            const uint32_t stg = sb + (uint32_t)(c & 1) * STAGE_BYTES;
            if (c < 3) ldg_A(av, g, c + 1, m0, N);  // overlap LDG with MMA

            const uint32_t AHb = stg, ALb = stg + TILE_BYTES;
            const uint32_t BHb = stg + 2 * TILE_BYTES, BLb = stg + 3 * TILE_BYTES;
#pragma unroll
            for (int ks = 0; ks < 4; ks++) {
                uint32_t ah[2][4], al[2][4];
#pragma unroll
                for (int f = 0; f < 2; f++) {
                    uint32_t ao = (uint32_t)(((mbase + f * 16 + a_row) * PCH +
                                              ks * 16 + a_kof) * 2);
                    ldsm_x4(ah[f], AHb + ao);
                    ldsm_x4(al[f], ALb + ao);
                }
#pragma unroll
                for (int pf = 0; pf < 2; pf++) {
                    uint32_t bh[4], bl[4];
                    uint32_t bo = (uint32_t)(((nbase + pf * 16 + b_row) * PCH +
                                              ks * 16 + b_kof) * 2);
                    ldsm_x4(bh, BHb + bo);
                    ldsm_x4(bl, BLb + bo);
#pragma unroll
                    for (int f = 0; f < 2; f++) {
                        mma_bf16(acc[f][2 * pf], ah[f], bh);
                        mma_bf16(acc[f][2 * pf], ah[f], bl);
                        mma_bf16(acc[f][2 * pf], al[f], bh);
                        mma_bf16(acc[f][2 * pf + 1], ah[f], bh + 2);
                        mma_bf16(acc[f][2 * pf + 1], ah[f], bl + 2);
                        mma_bf16(acc[f][2 * pf + 1], al[f], bh + 2);
                    }
                }
            }
            if (c < 3) {
                __syncthreads();  // all warps done reading next buffer's old data
                const uint32_t nsb = sb + (uint32_t)((c + 1) & 1) * STAGE_BYTES;
                cpB(g, c + 1, n0, nsb);
                CP_COMMIT;
                sts_A(av, smem + (size_t)((c + 1) & 1) * STAGE_BYTES);
                CP_WAIT0;
                __syncthreads();
            }
        }
        // fold tanh for this GEMM
#pragma unroll
        for (int f = 0; f < 2; f++)
#pragma unroll
            for (int nf = 0; nf < 4; nf++)
#pragma unroll
                for (int i = 0; i < 4; i++) osum[f][nf][i] += tanhf(acc[f][nf][i]);
    }

    // residual + store. Fragment: regs {0,1} -> row r, cols col, col+1; {2,3} -> row+8.
    const int r0 = m0 + mbase + (lane >> 2);
    const int cb = n0 + nbase + (lane & 3) * 2;
#pragma unroll
    for (int f = 0; f < 2; f++)
#pragma unroll
        for (int hh = 0; hh < 2; hh++) {
            int row = r0 + f * 16 + hh * 8;
            if (row < N) {
#pragma unroll
                for (int nf = 0; nf < 4; nf++) {
                    int col = cb + nf * 8;
                    float2 ev = *reinterpret_cast<const float2*>(
                        ent + (size_t)row * H + col);
                    float2 o = make_float2(ev.x + osum[f][nf][2 * hh],
                                           ev.y + osum[f][nf][2 * hh + 1]);
                    *reinterpret_cast<float2*>(out + (size_t)row * H + col) = o;
                }
            }
        }
}

// ---------------------------------------------------------------- pass 5: out_rel = rel_emb @ rel_w
__global__ void k_rel(const float* __restrict__ rel, const float* __restrict__ rw,
                      float* __restrict__ out, int R2) {
    __shared__ float row[H];
    int r = blockIdx.x;
    int tid = threadIdx.x;
    row[tid] = rel[(size_t)r * H + tid];
    __syncthreads();
    float acc = 0.f;
#pragma unroll 8
    for (int k = 0; k < H; k++)
        acc += row[k] * rw[(size_t)k * H + tid];
    out[(size_t)r * H + tid] = acc;
}

// ---------------------------------------------------------------- launch
extern "C" void kernel_launch(void* const* d_in, const int* in_sizes, int n_in,
                              void* d_out, int out_size) {
    const float* ent    = (const float*)d_in[0];
    const float* rel    = (const float*)d_in[1];
    const float* w_edge = (const float*)d_in[2];
    const float* w_node = (const float*)d_in[3];
    const float* w_comp = (const float*)d_in[4];
    const float* rel_w  = (const float*)d_in[5];
    const int* src = (const int*)d_in[6];
    const int* dst = (const int*)d_in[7];
    const int* rid = (const int*)d_in[8];
    const int* nid = (const int*)d_in[9];
    const int N  = in_sizes[0] / H;
    const int R2 = in_sizes[1] / H;
    const int E  = in_sizes[6];
    float* out_ent = (float*)d_out;
    float* out_rel = out_ent + (size_t)N * H;

    static bool attr_set = false;
    if (!attr_set) {
        cudaFuncSetAttribute(k_gemm_mma, cudaFuncAttributeMaxDynamicSharedMemorySize,
                             GEMM_SMEM);
        attr_set = true;
    }

    k_init<<<2048, 256>>>(N);
    k_wconv<<<(3 * H * H + 255) / 256, 256>>>(w_edge, w_node, w_comp);
    k_scores<<<(E + 7) / 8, 256>>>(ent, rel, src, dst, rid, nid, E);
    k_exps<<<(E + 255) / 256, 256>>>(dst, E);
    k_scatter<<<(E + 7) / 8, 256>>>(ent, rel, src, dst, rid, nid, E);
    dim3 gg(2, (N + 127) / 128);
    k_gemm_mma<<<gg, 512, GEMM_SMEM>>>(ent, out_ent, N);
    if (R2 > 0) k_rel<<<R2, 256>>>(rel, rel_w, out_rel, R2);
}

// round 7
// speedup vs baseline: 2.0217x; 1.2817x over previous
#include <cuda_runtime.h>
#include <cuda_bf16.h>
#include <cstdint>

#define H 256
#define NMAX 100000
#define EMAX 320000

// ---------------- scratch (__device__ globals; no allocation allowed) --------
__device__ float          g_agg[3][NMAX * H];   // per-dst aggregated rows (fp32)
__device__ unsigned short g_wh[3][H * H];       // W^T hi (bf16 bits), [n][k]
__device__ unsigned short g_wl[3][H * H];       // W^T lo (bf16 bits)
__device__ int            g_deg[NMAX];          // per-dst degree
__device__ int            g_off[NMAX];          // exclusive prefix (CSR row start)
__device__ int            g_cur[NMAX];          // permute cursors
__device__ int            g_eid[EMAX];          // dst-sorted edge ids
__device__ int            g_bsum[128];          // scan block sums

// ---------------- helpers ----------------------------------------------------
__device__ __forceinline__ uint32_t smem_u32(const void* p) {
    uint32_t a;
    asm("{ .reg .u64 t; cvta.to.shared.u64 t, %1; cvt.u32.u64 %0, t; }"
        : "=r"(a) : "l"(p));
    return a;
}
__device__ __forceinline__ void ldsm_x4(uint32_t r[4], uint32_t addr) {
    asm volatile("ldmatrix.sync.aligned.m8n8.x4.shared.b16 {%0,%1,%2,%3}, [%4];"
                 : "=r"(r[0]), "=r"(r[1]), "=r"(r[2]), "=r"(r[3]) : "r"(addr));
}
__device__ __forceinline__ void mma_bf16(float d[4], const uint32_t a[4],
                                         const uint32_t b[2]) {
    asm volatile(
        "mma.sync.aligned.m16n8k16.row.col.f32.bf16.bf16.f32 "
        "{%0,%1,%2,%3}, {%4,%5,%6,%7}, {%8,%9}, {%0,%1,%2,%3};"
        : "+f"(d[0]), "+f"(d[1]), "+f"(d[2]), "+f"(d[3])
        : "r"(a[0]), "r"(a[1]), "r"(a[2]), "r"(a[3]), "r"(b[0]), "r"(b[1]));
}
__device__ __forceinline__ void cp16(uint32_t dst, const void* src) {
    asm volatile("cp.async.cg.shared.global [%0], [%1], 16;"
                 :: "r"(dst), "l"(src) : "memory");
}
#define CP_COMMIT asm volatile("cp.async.commit_group;" ::: "memory")
#define CP_WAIT0  asm volatile("cp.async.wait_group 0;" ::: "memory")

__device__ __forceinline__ float wsum(float v) {
#pragma unroll
    for (int o = 16; o; o >>= 1) v += __shfl_xor_sync(0xffffffffu, v, o);
    return v;
}

// ------------------------------------------------- W -> W^T bf16 hi/lo split
__global__ void k_wconv(const float* __restrict__ w0, const float* __restrict__ w1,
                        const float* __restrict__ w2) {
    int i = blockIdx.x * blockDim.x + threadIdx.x;
    if (i >= 3 * H * H) return;
    int g = i >> 16;
    int r = i & 0xFFFF;
    int k = r >> 8, n = r & 255;
    const float* w = (g == 0) ? w0 : (g == 1) ? w1 : w2;
    float v = w[k * H + n];
    __nv_bfloat16 hi = __float2bfloat16(v);
    float lo = v - __bfloat162float(hi);
    g_wh[g][n * H + k] = __bfloat16_as_ushort(hi);
    g_wl[g][n * H + k] = __bfloat16_as_ushort(__float2bfloat16(lo));
}

// ---------------------------------------------------------------- CSR build
__global__ void k_zero(int N) {
    int i = blockIdx.x * blockDim.x + threadIdx.x;
    if (i < N) { g_deg[i] = 0; g_cur[i] = 0; }
}
__global__ void k_hist(const int* __restrict__ dst, int E) {
    int e = blockIdx.x * blockDim.x + threadIdx.x;
    if (e < E) atomicAdd(&g_deg[dst[e]], 1);
}
__global__ void k_scan_block(int N) {
    __shared__ int sm[1024];
    int tid = threadIdx.x;
    int i = blockIdx.x * 1024 + tid;
    int v = (i < N) ? g_deg[i] : 0;
    sm[tid] = v;
    __syncthreads();
#pragma unroll
    for (int o = 1; o < 1024; o <<= 1) {
        int t = (tid >= o) ? sm[tid - o] : 0;
        __syncthreads();
        sm[tid] += t;
        __syncthreads();
    }
    if (i < N) g_off[i] = sm[tid] - v;  // exclusive
    if (tid == 1023) g_bsum[blockIdx.x] = sm[1023];
}
__global__ void k_scan_top(int nb) {
    if (threadIdx.x == 0 && blockIdx.x == 0) {
        int run = 0;
        for (int b = 0; b < nb; b++) { int t = g_bsum[b]; g_bsum[b] = run; run += t; }
    }
}
__global__ void k_scan_add(int N) {
    int i = blockIdx.x * blockDim.x + threadIdx.x;
    if (i < N) g_off[i] += g_bsum[i >> 10];
}
__global__ void k_permute(const int* __restrict__ dst, int E) {
    int e = blockIdx.x * blockDim.x + threadIdx.x;
    if (e >= E) return;
    int d = dst[e];
    int slot = g_off[d] + atomicAdd(&g_cur[d], 1);
    g_eid[slot] = e;
}

// ------------------------------------------ fused edge pass: warp per dst node
// Online softmax over the node's incoming edges for all three attention heads;
// accumulates e*a0, hs*a1, (hs*e)*a2 in registers; writes agg rows once (.cs).
__global__ __launch_bounds__(256) void k_edge(
    const float* __restrict__ ent, const float* __restrict__ rel,
    const int* __restrict__ src, const int* __restrict__ rid,
    const int* __restrict__ nid, int N) {
    int w = (blockIdx.x * 256 + threadIdx.x) >> 5;
    if (w >= N) return;
    const int lane = threadIdx.x & 31;
    const int d = w;
    const int dn = nid[d];
    const float4* ent4 = reinterpret_cast<const float4*>(ent);
    const float4* rel4 = reinterpret_cast<const float4*>(rel);
    const float4 hda = ent4[(size_t)dn * 64 + lane];
    const float4 hdb = ent4[(size_t)dn * 64 + lane + 32];

    const int off0 = g_off[d];
    const int deg = g_deg[d];

    float m0 = -1e30f, m1 = -1e30f, m2 = -1e30f;
    float s0 = 0.f, s1 = 0.f, s2 = 0.f;
    float4 a0a = {0, 0, 0, 0}, a0b = {0, 0, 0, 0};
    float4 a1a = {0, 0, 0, 0}, a1b = {0, 0, 0, 0};
    float4 a2a = {0, 0, 0, 0}, a2b = {0, 0, 0, 0};

    for (int j = 0; j < deg; j++) {
        int eid = g_eid[off0 + j];
        int sn = nid[src[eid]];
        int rr = rid[eid];
        float4 sa = ent4[(size_t)sn * 64 + lane];
        float4 sb = ent4[(size_t)sn * 64 + lane + 32];
        float4 ea = rel4[(size_t)rr * 64 + lane];
        float4 eb = rel4[(size_t)rr * 64 + lane + 32];
        // three dot products with hd
        float pe = ea.x * hda.x + ea.y * hda.y + ea.z * hda.z + ea.w * hda.w
                 + eb.x * hdb.x + eb.y * hdb.y + eb.z * hdb.z + eb.w * hdb.w;
        float pn = sa.x * hda.x + sa.y * hda.y + sa.z * hda.z + sa.w * hda.w
                 + sb.x * hdb.x + sb.y * hdb.y + sb.z * hdb.z + sb.w * hdb.w;
        float pc = sa.x * ea.x * hda.x + sa.y * ea.y * hda.y
                 + sa.z * ea.z * hda.z + sa.w * ea.w * hda.w
                 + sb.x * eb.x * hdb.x + sb.y * eb.y * hdb.y
                 + sb.z * eb.z * hdb.z + sb.w * eb.w * hdb.w;
        float de = wsum(pe), dn_ = wsum(pn), dc = wsum(pc);
        // online softmax updates (rescale running sums)
        float nm0 = fmaxf(m0, de), c0 = expf(m0 - nm0), w0 = expf(de - nm0);
        float nm1 = fmaxf(m1, dn_), c1 = expf(m1 - nm1), w1 = expf(dn_ - nm1);
        float nm2 = fmaxf(m2, dc), c2 = expf(m2 - nm2), w2 = expf(dc - nm2);
        m0 = nm0; m1 = nm1; m2 = nm2;
        s0 = s0 * c0 + w0; s1 = s1 * c1 + w1; s2 = s2 * c2 + w2;
        a0a.x = a0a.x * c0 + ea.x * w0; a0a.y = a0a.y * c0 + ea.y * w0;
        a0a.z = a0a.z * c0 + ea.z * w0; a0a.w = a0a.w * c0 + ea.w * w0;
        a0b.x = a0b.x * c0 + eb.x * w0; a0b.y = a0b.y * c0 + eb.y * w0;
        a0b.z = a0b.z * c0 + eb.z * w0; a0b.w = a0b.w * c0 + eb.w * w0;
        a1a.x = a1a.x * c1 + sa.x * w1; a1a.y = a1a.y * c1 + sa.y * w1;
        a1a.z = a1a.z * c1 + sa.z * w1; a1a.w = a1a.w * c1 + sa.w * w1;
        a1b.x = a1b.x * c1 + sb.x * w1; a1b.y = a1b.y * c1 + sb.y * w1;
        a1b.z = a1b.z * c1 + sb.z * w1; a1b.w = a1b.w * c1 + sb.w * w1;
        a2a.x = a2a.x * c2 + sa.x * ea.x * w2; a2a.y = a2a.y * c2 + sa.y * ea.y * w2;
        a2a.z = a2a.z * c2 + sa.z * ea.z * w2; a2a.w = a2a.w * c2 + sa.w * ea.w * w2;
        a2b.x = a2b.x * c2 + sb.x * eb.x * w2; a2b.y = a2b.y * c2 + sb.y * eb.y * w2;
        a2b.z = a2b.z * c2 + sb.z * eb.z * w2; a2b.w = a2b.w * c2 + sb.w * eb.w * w2;
    }
    float i0 = (s0 > 0.f) ? 1.f / s0 : 0.f;
    float i1 = (s1 > 0.f) ? 1.f / s1 : 0.f;
    float i2 = (s2 > 0.f) ? 1.f / s2 : 0.f;
    float4* r0 = reinterpret_cast<float4*>(g_agg[0] + (size_t)d * H);
    float4* r1 = reinterpret_cast<float4*>(g_agg[1] + (size_t)d * H);
    float4* r2 = reinterpret_cast<float4*>(g_agg[2] + (size_t)d * H);
    __stcs(r0 + lane,      make_float4(a0a.x * i0, a0a.y * i0, a0a.z * i0, a0a.w * i0));
    __stcs(r0 + lane + 32, make_float4(a0b.x * i0, a0b.y * i0, a0b.z * i0, a0b.w * i0));
    __stcs(r1 + lane,      make_float4(a1a.x * i1, a1a.y * i1, a1a.z * i1, a1a.w * i1));
    __stcs(r1 + lane + 32, make_float4(a1b.x * i1, a1b.y * i1, a1b.z * i1, a1b.w * i1));
    __stcs(r2 + lane,      make_float4(a2a.x * i2, a2a.y * i2, a2a.z * i2, a2a.w * i2));
    __stcs(r2 + lane + 32, make_float4(a2b.x * i2, a2b.y * i2, a2b.z * i2, a2b.w * i2));
}

// ---------------------------------------------------------------- mma.sync split-bf16 GEMM
// CTA: 128x128 tile of out_ent; 512 threads = 16 warps (4m x 4n), warp tile 32x32.
// For g in {0,1,2}: D = Ah@Bh + Ah@Bl + Al@Bh (f32 acc), tanh folded per g.
#define PCH 72                               // smem pitch (bf16 elems) = 144 B
#define KC 64
#define TILE_BYTES (128 * PCH * 2)           // 18432
#define STAGE_BYTES (4 * TILE_BYTES)         // Ah | Al | Bh | Bl = 73728
#define GEMM_SMEM (2 * STAGE_BYTES)          // 147456

__device__ __forceinline__ void ldg_A(float4 av[2][2], int g, int c, int m0, int N) {
    const float* A = g_agg[g];
    const int k0 = c * KC;
    const int tid = threadIdx.x;
#pragma unroll
    for (int q = 0; q < 2; q++) {
        int idx = q * 512 + tid;
        int row = idx >> 3, oct = idx & 7;
        int gr = m0 + row;
        if (gr < N) {
            const float4* p = reinterpret_cast<const float4*>(
                A + (size_t)gr * H + k0 + oct * 8);
            av[q][0] = p[0];
            av[q][1] = p[1];
        } else {
            av[q][0] = make_float4(0.f, 0.f, 0.f, 0.f);
            av[q][1] = make_float4(0.f, 0.f, 0.f, 0.f);
        }
    }
}
__device__ __forceinline__ void split2(float x, float y, uint32_t& h, uint32_t& l) {
    __nv_bfloat16 hx = __float2bfloat16(x), hy = __float2bfloat16(y);
    __nv_bfloat16 lx = __float2bfloat16(x - __bfloat162float(hx));
    __nv_bfloat16 ly = __float2bfloat16(y - __bfloat162float(hy));
    h = ((uint32_t)__bfloat16_as_ushort(hy) << 16) | __bfloat16_as_ushort(hx);
    l = ((uint32_t)__bfloat16_as_ushort(ly) << 16) | __bfloat16_as_ushort(lx);
}
__device__ __forceinline__ void sts_A(const float4 av[2][2], char* stage) {
    const int tid = threadIdx.x;
#pragma unroll
    for (int q = 0; q < 2; q++) {
        int idx = q * 512 + tid;
        int row = idx >> 3, oct = idx & 7;
        uint4 hi, lo;
        split2(av[q][0].x, av[q][0].y, hi.x, lo.x);
        split2(av[q][0].z, av[q][0].w, hi.y, lo.y);
        split2(av[q][1].x, av[q][1].y, hi.z, lo.z);
        split2(av[q][1].z, av[q][1].w, hi.w, lo.w);
        uint32_t off = (uint32_t)(row * (PCH * 2) + oct * 16);
        *reinterpret_cast<uint4*>(stage + off) = hi;
        *reinterpret_cast<uint4*>(stage + TILE_BYTES + off) = lo;
    }
}
__device__ __forceinline__ void cpB(int g, int c, int n0, uint32_t stage_sb) {
    const int tid = threadIdx.x;
    const int k0 = c * KC;
#pragma unroll
    for (int q = 0; q < 2; q++) {
        int idx = q * 512 + tid;
        int row = idx >> 3, oct = idx & 7;
        uint32_t off = (uint32_t)(row * (PCH * 2) + oct * 16);
        size_t gi = (size_t)(n0 + row) * H + k0 + oct * 8;
        cp16(stage_sb + 2 * TILE_BYTES + off, g_wh[g] + gi);
        cp16(stage_sb + 3 * TILE_BYTES + off, g_wl[g] + gi);
    }
}

__global__ __launch_bounds__(512, 1)
void k_gemm_mma(const float* __restrict__ ent, float* __restrict__ out, int N) {
    extern __shared__ char smem[];
    const uint32_t sb = smem_u32(smem);
    const int tid = threadIdx.x;
    const int lane = tid & 31, wid = tid >> 5;
    const int wm = wid >> 2, wn = wid & 3;
    const int mbase = wm * 32, nbase = wn * 32;
    const int m0 = blockIdx.y * 128, n0 = blockIdx.x * 128;

    const int a_row = (lane & 7) + ((lane >> 3) & 1) * 8;
    const int a_kof = (lane >> 4) * 8;
    const int b_row = (lane & 7) + (lane >> 4) * 8;
    const int b_kof = ((lane >> 3) & 1) * 8;

    float osum[2][4][4];
#pragma unroll
    for (int f = 0; f < 2; f++)
#pragma unroll
        for (int nf = 0; nf < 4; nf++)
#pragma unroll
            for (int i = 0; i < 4; i++) osum[f][nf][i] = 0.f;

#pragma unroll 1
    for (int g = 0; g < 3; g++) {
        float acc[2][4][4];
#pragma unroll
        for (int f = 0; f < 2; f++)
#pragma unroll
            for (int nf = 0; nf < 4; nf++)
#pragma unroll
                for (int i = 0; i < 4; i++) acc[f][nf][i] = 0.f;

        float4 av[2][2];
        ldg_A(av, g, 0, m0, N);
        cpB(g, 0, n0, sb);
        CP_COMMIT;
        sts_A(av, smem);
        CP_WAIT0;
        __syncthreads();

#pragma unroll 1
        for (int c = 0; c < 4; c++) {
            const uint32_t stg = sb + (uint32_t)(c & 1) * STAGE_BYTES;
            if (c < 3) ldg_A(av, g, c + 1, m0, N);

            const uint32_t AHb = stg, ALb = stg + TILE_BYTES;
            const uint32_t BHb = stg + 2 * TILE_BYTES, BLb = stg + 3 * TILE_BYTES;
#pragma unroll
            for (int ks = 0; ks < 4; ks++) {
                uint32_t ah[2][4], al[2][4];
#pragma unroll
                for (int f = 0; f < 2; f++) {
                    uint32_t ao = (uint32_t)(((mbase + f * 16 + a_row) * PCH +
                                              ks * 16 + a_kof) * 2);
                    ldsm_x4(ah[f], AHb + ao);
                    ldsm_x4(al[f], ALb + ao);
                }
#pragma unroll
                for (int pf = 0; pf < 2; pf++) {
                    uint32_t bh[4], bl[4];
                    uint32_t bo = (uint32_t)(((nbase + pf * 16 + b_row) * PCH +
                                              ks * 16 + b_kof) * 2);
                    ldsm_x4(bh, BHb + bo);
                    ldsm_x4(bl, BLb + bo);
#pragma unroll
                    for (int f = 0; f < 2; f++) {
                        mma_bf16(acc[f][2 * pf], ah[f], bh);
                        mma_bf16(acc[f][2 * pf], ah[f], bl);
                        mma_bf16(acc[f][2 * pf], al[f], bh);
                        mma_bf16(acc[f][2 * pf + 1], ah[f], bh + 2);
                        mma_bf16(acc[f][2 * pf + 1], ah[f], bl + 2);
                        mma_bf16(acc[f][2 * pf + 1], al[f], bh + 2);
                    }
                }
            }
            if (c < 3) {
                __syncthreads();
                const uint32_t nsb = sb + (uint32_t)((c + 1) & 1) * STAGE_BYTES;
                cpB(g, c + 1, n0, nsb);
                CP_COMMIT;
                sts_A(av, smem + (size_t)((c + 1) & 1) * STAGE_BYTES);
                CP_WAIT0;
                __syncthreads();
            }
        }
#pragma unroll
        for (int f = 0; f < 2; f++)
#pragma unroll
            for (int nf = 0; nf < 4; nf++)
#pragma unroll
                for (int i = 0; i < 4; i++) osum[f][nf][i] += tanhf(acc[f][nf][i]);
    }

    const int r0 = m0 + mbase + (lane >> 2);
    const int cb = n0 + nbase + (lane & 3) * 2;
#pragma unroll
    for (int f = 0; f < 2; f++)
#pragma unroll
        for (int hh = 0; hh < 2; hh++) {
            int row = r0 + f * 16 + hh * 8;
            if (row < N) {
#pragma unroll
                for (int nf = 0; nf < 4; nf++) {
                    int col = cb + nf * 8;
                    float2 ev = *reinterpret_cast<const float2*>(
                        ent + (size_t)row * H + col);
                    float2 o = make_float2(ev.x + osum[f][nf][2 * hh],
                                           ev.y + osum[f][nf][2 * hh + 1]);
                    *reinterpret_cast<float2*>(out + (size_t)row * H + col) = o;
                }
            }
        }
}

// ---------------------------------------------------------------- out_rel = rel_emb @ rel_w
__global__ void k_rel(const float* __restrict__ rel, const float* __restrict__ rw,
                      float* __restrict__ out, int R2) {
    __shared__ float row[H];
    int r = blockIdx.x;
    int tid = threadIdx.x;
    row[tid] = rel[(size_t)r * H + tid];
    __syncthreads();
    float acc = 0.f;
#pragma unroll 8
    for (int k = 0; k < H; k++)
        acc += row[k] * rw[(size_t)k * H + tid];
    out[(size_t)r * H + tid] = acc;
}

// ---------------------------------------------------------------- launch
extern "C" void kernel_launch(void* const* d_in, const int* in_sizes, int n_in,
                              void* d_out, int out_size) {
    const float* ent    = (const float*)d_in[0];
    const float* rel    = (const float*)d_in[1];
    const float* w_edge = (const float*)d_in[2];
    const float* w_node = (const float*)d_in[3];
    const float* w_comp = (const float*)d_in[4];
    const float* rel_w  = (const float*)d_in[5];
    const int* src = (const int*)d_in[6];
    const int* dst = (const int*)d_in[7];
    const int* rid = (const int*)d_in[8];
    const int* nid = (const int*)d_in[9];
    const int N  = in_sizes[0] / H;
    const int R2 = in_sizes[1] / H;
    const int E  = in_sizes[6];
    float* out_ent = (float*)d_out;
    float* out_rel = out_ent + (size_t)N * H;

    static bool attr_set = false;
    if (!attr_set) {
        cudaFuncSetAttribute(k_gemm_mma, cudaFuncAttributeMaxDynamicSharedMemorySize,
                             GEMM_SMEM);
        attr_set = true;
    }

    const int nb_scan = (N + 1023) / 1024;
    k_wconv<<<(3 * H * H + 255) / 256, 256>>>(w_edge, w_node, w_comp);
    k_zero<<<(N + 255) / 256, 256>>>(N);
    k_hist<<<(E + 255) / 256, 256>>>(dst, E);
    k_scan_block<<<nb_scan, 1024>>>(N);
    k_scan_top<<<1, 32>>>(nb_scan);
    k_scan_add<<<(N + 255) / 256, 256>>>(N);
    k_permute<<<(E + 255) / 256, 256>>>(dst, E);
    k_edge<<<(N + 7) / 8, 256>>>(ent, rel, src, rid, nid, N);
    dim3 gg(2, (N + 127) / 128);
    k_gemm_mma<<<gg, 512, GEMM_SMEM>>>(ent, out_ent, N);
    if (R2 > 0) k_rel<<<R2, 256>>>(rel, rel_w, out_rel, R2);
}